// round 2
// baseline (speedup 1.0000x reference)
#include <cuda_runtime.h>

#define BB 32
#define SS 2048
#define DD 1024
#define KATT 10
#define CHUNKS 32
#define ROWS_PER_CHUNK (SS / CHUNKS)   // 64
#define D4 (DD / 4)                    // 256 float4 per row

// Scratch (no allocation allowed)
__device__ float g_partial[BB * CHUNKS * DD];  // 4 MB
__device__ float g_vraw[BB * DD];
__device__ float g_vn[BB * DD];
__device__ float g_corr[BB * DD];

// ---------------------------------------------------------------------------
// k1: partial sums over sequence chunks.
// grid = BB*CHUNKS blocks, 256 threads. Block (b,c) sums 64 rows of [b].
// ---------------------------------------------------------------------------
__global__ void __launch_bounds__(256) k1_partial(const float* __restrict__ h) {
    const float4* h4 = (const float4*)h;
    int b = blockIdx.x >> 5;
    int c = blockIdx.x & 31;
    const float4* p = h4 + ((size_t)b << 19) + (size_t)c * ROWS_PER_CHUNK * D4 + threadIdx.x;
    float4 acc = make_float4(0.f, 0.f, 0.f, 0.f);
#pragma unroll 8
    for (int s = 0; s < ROWS_PER_CHUNK; ++s) {
        float4 v = p[(size_t)s * D4];
        acc.x += v.x; acc.y += v.y; acc.z += v.z; acc.w += v.w;
    }
    ((float4*)g_partial)[(b * CHUNKS + c) * D4 + threadIdx.x] = acc;
}

// ---------------------------------------------------------------------------
// k1b: reduce the 32 chunk-partials -> v_raw (mean over S).
// grid = BB blocks, 256 threads.
// ---------------------------------------------------------------------------
__global__ void __launch_bounds__(256) k1b_reduce() {
    int b = blockIdx.x;
    int t = threadIdx.x;
    const float4* p4 = (const float4*)g_partial;
    float4 acc = make_float4(0.f, 0.f, 0.f, 0.f);
#pragma unroll
    for (int c = 0; c < CHUNKS; ++c) {
        float4 v = p4[(b * CHUNKS + c) * D4 + t];
        acc.x += v.x; acc.y += v.y; acc.z += v.z; acc.w += v.w;
    }
    const float inv = 1.0f / (float)SS;
    acc.x *= inv; acc.y *= inv; acc.z *= inv; acc.w *= inv;
    ((float4*)g_vraw)[b * D4 + t] = acc;
}

// ---------------------------------------------------------------------------
// k2: all the small math. One block, 1024 threads (32 warps).
//   phase 0: attractor norm scales (warps 0..9)
//   phase A: whitening over batch (thread d handles dim d)
//   phase B: cosine + argmax (warp w handles batch row w)
//   phase C: correction = v_snapped - v_raw
// ---------------------------------------------------------------------------
__global__ void __launch_bounds__(1024, 1) k2_small(const float* __restrict__ att) {
    __shared__ float s_s1[KATT];    // 1/max(|a|,1e-8)
    __shared__ float s_cs[KATT];    // combined cosine scale: s1 / max(|a|*s1, 1e-12)
    __shared__ float s_alpha[BB];
    __shared__ int   s_best[BB];

    int tid = threadIdx.x;
    int lane = tid & 31;
    int wid = tid >> 5;

    // --- phase 0: attractor scales ---
    if (wid < KATT) {
        float s = 0.f;
        for (int j = lane; j < DD; j += 32) {
            float a = att[wid * DD + j];
            s += a * a;
        }
#pragma unroll
        for (int o = 16; o; o >>= 1) s += __shfl_xor_sync(0xffffffff, s, o);
        if (lane == 0) {
            float n1 = sqrtf(s);
            float s1 = 1.0f / fmaxf(n1, 1e-8f);
            float n2 = n1 * s1;                 // |att| after first normalize
            s_s1[wid] = s1;
            s_cs[wid] = s1 / fmaxf(n2, 1e-12f);
        }
    }

    // --- phase A: whitening (two-pass mean/var over batch) ---
    {
        int d = tid;
        float sum = 0.f;
#pragma unroll
        for (int b = 0; b < BB; ++b) sum += g_vraw[b * DD + d];
        float mean = sum * (1.0f / (float)BB);
        float s2 = 0.f;
#pragma unroll
        for (int b = 0; b < BB; ++b) {
            float t = g_vraw[b * DD + d] - mean;
            s2 += t * t;
        }
        float var = s2 * (1.0f / (float)BB);
        float inv = 1.0f / sqrtf(var + 1e-8f);
#pragma unroll
        for (int b = 0; b < BB; ++b)
            g_vn[b * DD + d] = (g_vraw[b * DD + d] - mean) * inv;
    }
    __syncthreads();

    // --- phase B: cosine similarity + argmax (warp w -> batch row w) ---
    {
        int b = wid;
        float vnr[32];
#pragma unroll
        for (int j = 0; j < 32; ++j) vnr[j] = g_vn[b * DD + lane + 32 * j];
        float best = -1e30f;
        int bi = 0;
        for (int k = 0; k < KATT; ++k) {
            float p = 0.f;
#pragma unroll
            for (int j = 0; j < 32; ++j) p += vnr[j] * att[k * DD + lane + 32 * j];
#pragma unroll
            for (int o = 16; o; o >>= 1) p += __shfl_xor_sync(0xffffffff, p, o);
            float cosv = p * s_cs[k];
            if (cosv > best) { best = cosv; bi = k; }   // first max (strict >) == jnp.argmax
        }
        if (lane == 0) {
            s_alpha[b] = 0.3f * (1.0f - best);
            s_best[b] = bi;
        }
    }
    __syncthreads();

    // --- phase C: correction = v_norm + alpha*clip(closest - v_norm) - v_raw ---
    {
        int d = tid;
#pragma unroll
        for (int b = 0; b < BB; ++b) {
            float vn = g_vn[b * DD + d];
            int k = s_best[b];
            float closest = att[k * DD + d] * s_s1[k];
            float delta = fminf(fmaxf(closest - vn, -0.5f), 0.5f);
            g_corr[b * DD + d] = vn + s_alpha[b] * delta - g_vraw[b * DD + d];
        }
    }
}

// ---------------------------------------------------------------------------
// k3: out[b][s][d] = h[b][s][d] + corr[b][d], float4 streaming.
// grid = 65536 blocks x 256 threads, one float4 per thread.
// ---------------------------------------------------------------------------
__global__ void __launch_bounds__(256) k3_apply(const float* __restrict__ h,
                                                float* __restrict__ out) {
    unsigned i = blockIdx.x * blockDim.x + threadIdx.x;   // float4 index, < 2^24
    float4 v = ((const float4*)h)[i];
    unsigned d4 = i & (D4 - 1);          // float4 index within D row
    unsigned b = i >> 19;                // S*D/4 = 2^19 float4 per batch row
    float4 c = ((const float4*)g_corr)[(b << 8) + d4];
    v.x += c.x; v.y += c.y; v.z += c.z; v.w += c.w;
    ((float4*)out)[i] = v;
}

// ---------------------------------------------------------------------------
extern "C" void kernel_launch(void* const* d_in, const int* in_sizes, int n_in,
                              void* d_out, int out_size) {
    const float* hidden = (const float*)d_in[0];   // [32, 2048, 1024] f32
    const float* att    = (const float*)d_in[1];   // [10, 1024] f32
    float* out = (float*)d_out;

    k1_partial<<<BB * CHUNKS, 256>>>(hidden);
    k1b_reduce<<<BB, 256>>>();
    k2_small<<<1, 1024>>>(att);
    const unsigned total4 = (unsigned)BB * SS * D4;       // 16,777,216
    k3_apply<<<total4 / 256, 256>>>(hidden, out);
}